// round 16
// baseline (speedup 1.0000x reference)
#include <cuda_runtime.h>
#include <math.h>
#include <stdint.h>

#define BATCH   2
#define CCH     1024
#define HW      1600
#define MTOK    (BATCH*HW)
#define HEADS   16
#define DH      64
#define CTXL    77
#define CTXP    96          // padded ld (K%32==0 for KT32 GEMM)
#define FFD     4096
#define GN_GROUPS 32
#define GN_EPS  1e-6f
#define LN_EPS  1e-5f

__device__ float g_t   [MTOK * CCH];
__device__ float g_tmp [MTOK * CCH];
__device__ float g_qkv [MTOK * 3 * CCH];
__device__ float g_ao  [MTOK * CCH];
__device__ float g_scores[(size_t)BATCH * HEADS * HW * CTXP];
__device__ float g_ffh [MTOK * 2 * FFD];
__device__ float g_ffa [MTOK * FFD];
__device__ float g_w3  [CCH * 3 * CCH];
__device__ float g_w2c [CCH * 2 * CCH];
__device__ float g_w1i [CCH * 2 * FFD];
__device__ float g_b1i [2 * FFD];

__device__ __forceinline__ float blockReduceSum(float v) {
    __shared__ float sh[32];
    int lane = threadIdx.x & 31, wid = threadIdx.x >> 5;
#pragma unroll
    for (int o = 16; o > 0; o >>= 1) v += __shfl_down_sync(0xffffffffu, v, o);
    if (lane == 0) sh[wid] = v;
    __syncthreads();
    int nw = (blockDim.x + 31) >> 5;
    v = (threadIdx.x < nw) ? sh[threadIdx.x] : 0.f;
    if (wid == 0) {
#pragma unroll
        for (int o = 16; o > 0; o >>= 1) v += __shfl_down_sync(0xffffffffu, v, o);
        if (lane == 0) sh[0] = v;
    }
    __syncthreads();
    float r = sh[0];
    __syncthreads();
    return r;
}

__device__ __forceinline__ float blockReduceMax(float v) {
    __shared__ float sh[32];
    int lane = threadIdx.x & 31, wid = threadIdx.x >> 5;
#pragma unroll
    for (int o = 16; o > 0; o >>= 1) v = fmaxf(v, __shfl_down_sync(0xffffffffu, v, o));
    if (lane == 0) sh[wid] = v;
    __syncthreads();
    int nw = (blockDim.x + 31) >> 5;
    v = (threadIdx.x < nw) ? sh[threadIdx.x] : -INFINITY;
    if (wid == 0) {
#pragma unroll
        for (int o = 16; o > 0; o >>= 1) v = fmaxf(v, __shfl_down_sync(0xffffffffu, v, o));
        if (lane == 0) sh[0] = v;
    }
    __syncthreads();
    float r = sh[0];
    __syncthreads();
    return r;
}

__global__ void groupnorm_kernel(const float* __restrict__ x, const float* __restrict__ s,
                                 const float* __restrict__ bgn, float* __restrict__ out) {
    int b = blockIdx.x / GN_GROUPS;
    int g = blockIdx.x % GN_GROUPS;
    const int CPG = CCH / GN_GROUPS, NEL = CPG * HW;
    const float* xp = x + ((size_t)b * CCH + (size_t)g * CPG) * HW;
    float sum = 0.f, sq = 0.f;
    for (int i = threadIdx.x; i < NEL; i += blockDim.x) {
        float v = xp[i]; sum += v; sq += v * v;
    }
    sum = blockReduceSum(sum); sq = blockReduceSum(sq);
    float mean = sum / (float)NEL;
    float inv = rsqrtf(sq / (float)NEL - mean * mean + GN_EPS);
    for (int i = threadIdx.x; i < NEL; i += blockDim.x) {
        int ci = i / HW, p = i % HW, c = g * CPG + ci;
        out[((size_t)b * HW + p) * CCH + c] = (xp[i] - mean) * inv * s[c] + bgn[c];
    }
}

// fused: y = sum4(p)(+bias)(+res) -> tOut; layernorm(y) -> nOut
__global__ void reduce4_ln_kernel(const float* __restrict__ p, const float* __restrict__ bias,
                                  const float* __restrict__ res, float* __restrict__ tOut,
                                  const float* __restrict__ s, const float* __restrict__ bln,
                                  float* __restrict__ nOut) {
    int row = blockIdx.x;
    const size_t MN = (size_t)MTOK * CCH;
    const int tid = threadIdx.x;
    const size_t base = (size_t)row * CCH + tid * 4;
    float4 a = *reinterpret_cast<const float4*>(p + base);
    float4 b2 = *reinterpret_cast<const float4*>(p + base + MN);
    float4 c2 = *reinterpret_cast<const float4*>(p + base + 2 * MN);
    float4 d2 = *reinterpret_cast<const float4*>(p + base + 3 * MN);
    float4 y;
    y.x = a.x + b2.x + c2.x + d2.x;
    y.y = a.y + b2.y + c2.y + d2.y;
    y.z = a.z + b2.z + c2.z + d2.z;
    y.w = a.w + b2.w + c2.w + d2.w;
    if (bias) {
        const float4 bb = *reinterpret_cast<const float4*>(bias + tid * 4);
        y.x += bb.x; y.y += bb.y; y.z += bb.z; y.w += bb.w;
    }
    if (res) {
        const float4 rr = *reinterpret_cast<const float4*>(res + base);
        y.x += rr.x; y.y += rr.y; y.z += rr.z; y.w += rr.w;
    }
    *reinterpret_cast<float4*>(tOut + base) = y;
    float sum = y.x + y.y + y.z + y.w;
    float sq = y.x * y.x + y.y * y.y + y.z * y.z + y.w * y.w;
    sum = blockReduceSum(sum); sq = blockReduceSum(sq);
    float mean = sum / (float)CCH;
    float inv = rsqrtf(sq / (float)CCH - mean * mean + LN_EPS);
    const float4 ss = *reinterpret_cast<const float4*>(s + tid * 4);
    const float4 lb = *reinterpret_cast<const float4*>(bln + tid * 4);
    float4 o;
    o.x = (y.x - mean) * inv * ss.x + lb.x;
    o.y = (y.y - mean) * inv * ss.y + lb.y;
    o.z = (y.z - mean) * inv * ss.z + lb.z;
    o.w = (y.w - mean) * inv * ss.w + lb.w;
    *reinterpret_cast<float4*>(nOut + base) = o;
}

__global__ void prep_w1_kernel(const float* __restrict__ w1, const float* __restrict__ b1,
                               float* __restrict__ w1i, float* __restrict__ b1i) {
    size_t idx = (size_t)blockIdx.x * blockDim.x + threadIdx.x;
    size_t total = (size_t)CCH * FFD;
    if (idx >= total) return;
    size_t k = idx / FFD, j = idx % FFD;
    w1i[k * 2 * FFD + 2 * j    ] = w1[k * 2 * FFD + j];
    w1i[k * 2 * FFD + 2 * j + 1] = w1[k * 2 * FFD + FFD + j];
    if (k == 0) {
        b1i[2 * j    ] = b1[j];
        b1i[2 * j + 1] = b1[FFD + j];
    }
}

__device__ __forceinline__ float f2tf32(float x) {
    uint32_t u;
    asm("cvt.rna.tf32.f32 %0, %1;" : "=r"(u) : "f"(x));
    return __uint_as_float(u);
}

__device__ __forceinline__ void mma4(float c[4], const float a[4], float b0, float b1) {
    asm volatile(
        "mma.sync.aligned.m16n8k8.row.col.f32.tf32.tf32.f32 "
        "{%0,%1,%2,%3}, {%4,%5,%6,%7}, {%8,%9}, {%0,%1,%2,%3};"
        : "+f"(c[0]), "+f"(c[1]), "+f"(c[2]), "+f"(c[3])
        : "r"(__float_as_uint(a[0])), "r"(__float_as_uint(a[1])),
          "r"(__float_as_uint(a[2])), "r"(__float_as_uint(a[3])),
          "r"(__float_as_uint(b0)), "r"(__float_as_uint(b1)));
}

// ===== fragment-packed smem layout (exact element addresses, within chunk) ===
__device__ __forceinline__ int offAe(int row, int k) {
    int L = ((row & 7) << 2) | (k & 3);
    int g2 = L ^ (L >> 3);
    return (row >> 4) * 292 + ((k >> 3) & 1) * 136 + g2 * 4 +
           ((row >> 3) & 1) + (((k >> 2) & 1) << 1);
}
__device__ __forceinline__ int offBe(int n, int k) {
    int L = ((n & 7) << 2) | (k & 3);
    int g2 = L ^ (L >> 3);
    return (n >> 4) * 292 + ((k >> 3) & 1) * 136 + g2 * 4 +
           (((n >> 3) & 1) << 1) + ((k >> 2) & 1);
}

// ================= flash attention (verified round 12; KT16 internal) =======
#define FA_Q  0
#define FA_K  9344
#define FA_V  18688
#define FA_P  28032
#define FA_ST 46720
#define FA_SMEM_BYTES ((46720 + 896) * 4)

__global__ __launch_bounds__(256)
void flash_kernel(const float* __restrict__ qkv, float* __restrict__ ao) {
    extern __shared__ float S[];
    float* Qs = S + FA_Q;
    float* Ks = S + FA_K;
    float* Vs = S + FA_V;
    float* Ps = S + FA_P;
    float* mpart = S + FA_ST;
    float* lpart = mpart + 256;
    float* mrun  = lpart + 256;
    float* fac   = mrun + 128;
    float* lrun  = fac + 128;

    const int tid = threadIdx.x, wid = tid >> 5, lane = tid & 31;
    const int wr = wid >> 1, wc = wid & 1, gp = lane >> 2, tg = lane & 3;
    const int fl = (lane ^ (lane >> 3)) * 4;
    const int qb = blockIdx.y;
    const int bh = blockIdx.z;
    const int b = bh >> 4, h = bh & 15;
    const size_t bhbase = (size_t)b * HW * 3072 + (size_t)h * 64;
    const float* Qg = qkv + bhbase;
    const float* Kg = qkv + CCH + bhbase;
    const float* Vg = qkv + 2 * CCH + bhbase;

#pragma unroll
    for (int u = 0; u < 8; u++) {
        int e = u * 256 + tid;
        int row = e >> 4, q4 = e & 15;
        int gr = qb * 128 + row;
        if (gr >= HW) gr = qb * 128;
        const float4 v = *(reinterpret_cast<const float4*>(Qg + (size_t)gr * 3072) + q4);
        int c = (row >> 1) & 3;
        int base = (q4 >> 2) * 2336 + offAe(row, (q4 * 4) & 15) - (c << 2);
        Qs[base + ((0 ^ c) << 2)] = f2tf32(v.x * 0.125f);
        Qs[base + ((1 ^ c) << 2)] = f2tf32(v.y * 0.125f);
        Qs[base + ((2 ^ c) << 2)] = f2tf32(v.z * 0.125f);
        Qs[base + ((3 ^ c) << 2)] = f2tf32(v.w * 0.125f);
    }
    if (tid < 128) { mrun[tid] = -INFINITY; lrun[tid] = 0.f; }

    float accO[2][4][4];
#pragma unroll
    for (int i = 0; i < 2; i++)
#pragma unroll
        for (int j = 0; j < 4; j++)
#pragma unroll
            for (int q = 0; q < 4; q++) accO[i][j][q] = 0.f;

    const int aR  = wr * 2 * 292 + fl;
    const int bRs = wc * 4 * 292 + fl;
    const int bRo = wc * 2 * 292 + fl;
    const int KVT = 13;

    for (int t = 0; t < KVT; t++) {
        __syncthreads();
#pragma unroll
        for (int u = 0; u < 8; u++) {
            int e = u * 256 + tid;
            int row = e >> 4, q4 = e & 15;
            int gr = t * 128 + row;
            if (gr >= HW) gr = t * 128;
            const float4 kv4 = *(reinterpret_cast<const float4*>(Kg + (size_t)gr * 3072) + q4);
            int c = (row >> 1) & 3;
            int kb = (q4 >> 2) * 2336 + offBe(row, (q4 * 4) & 15) - (c << 2);
            Ks[kb + ((0 ^ c) << 2)] = f2tf32(kv4.x);
            Ks[kb + ((1 ^ c) << 2)] = f2tf32(kv4.y);
            Ks[kb + ((2 ^ c) << 2)] = f2tf32(kv4.z);
            Ks[kb + ((3 ^ c) << 2)] = f2tf32(kv4.w);
            const float4 vv = *(reinterpret_cast<const float4*>(Vg + (size_t)gr * 3072) + q4);
            int n0 = q4 * 4;
            Vs[(row >> 4) * 1168 + offBe(n0 + 0, row & 15)] = f2tf32(vv.x);
            Vs[(row >> 4) * 1168 + offBe(n0 + 1, row & 15)] = f2tf32(vv.y);
            Vs[(row >> 4) * 1168 + offBe(n0 + 2, row & 15)] = f2tf32(vv.z);
            Vs[(row >> 4) * 1168 + offBe(n0 + 3, row & 15)] = f2tf32(vv.w);
        }
        __syncthreads();

        float acc[2][8][4];
#pragma unroll
        for (int i = 0; i < 2; i++)
#pragma unroll
            for (int j = 0; j < 8; j++)
#pragma unroll
                for (int q = 0; q < 4; q++) acc[i][j][q] = 0.f;
#pragma unroll
        for (int kt = 0; kt < 4; kt++) {
            const float* sa = Qs + kt * 2336;
            const float* sb = Ks + kt * 2336;
#pragma unroll
            for (int ks = 0; ks < 2; ks++) {
                float4 af0 = *reinterpret_cast<const float4*>(sa + aR + ks * 136);
                float4 af1 = *reinterpret_cast<const float4*>(sa + aR + 292 + ks * 136);
#pragma unroll
                for (int p = 0; p < 4; p++) {
                    float4 bf = *reinterpret_cast<const float4*>(sb + bRs + p * 292 + ks * 136);
                    mma4(acc[0][2 * p    ], reinterpret_cast<const float*>(&af0), bf.x, bf.y);
                    mma4(acc[1][2 * p    ], reinterpret_cast<const float*>(&af1), bf.x, bf.y);
                    mma4(acc[0][2 * p + 1], reinterpret_cast<const float*>(&af0), bf.z, bf.w);
                    mma4(acc[1][2 * p + 1], reinterpret_cast<const float*>(&af1), bf.z, bf.w);
                }
            }
        }

        const bool maskw = (t == KVT - 1) && (wc == 1);

        float mt[4];
#pragma unroll
        for (int s = 0; s < 4; s++) {
            int i = s >> 1, hh = s & 1;
            float m = -INFINITY;
            if (!maskw) {
#pragma unroll
                for (int j = 0; j < 8; j++)
                    m = fmaxf(m, fmaxf(acc[i][j][hh * 2], acc[i][j][hh * 2 + 1]));
            }
            m = fmaxf(m, __shfl_xor_sync(0xffffffffu, m, 1));
            m = fmaxf(m, __shfl_xor_sync(0xffffffffu, m, 2));
            mt[s] = m;
        }
        if (tg == 0) {
#pragma unroll
            for (int s = 0; s < 4; s++) {
                int row = wr * 32 + (s >> 1) * 16 + gp + (s & 1) * 8;
                mpart[wc * 128 + row] = mt[s];
            }
        }
        __syncthreads();
        if (tid < 128) {
            float mo = mrun[tid];
            float mn = fmaxf(mo, fmaxf(mpart[tid], mpart[128 + tid]));
            mrun[tid] = mn;
            fac[tid] = __expf(mo - mn);
        }
        __syncthreads();

        float lt[4];
#pragma unroll
        for (int s = 0; s < 4; s++) {
            int i = s >> 1, hh = s & 1;
            int row = wr * 32 + i * 16 + gp + hh * 8;
            float mn = mrun[row];
            float sum = 0.f;
#pragma unroll
            for (int j = 0; j < 8; j++) {
#pragma unroll
                for (int qq = 0; qq < 2; qq++) {
                    float p = maskw ? 0.f : __expf(acc[i][j][hh * 2 + qq] - mn);
                    sum += p;
                    int col = wc * 64 + j * 8 + tg * 2 + qq;
                    Ps[(col >> 4) * 2336 + offAe(row, col & 15)] = f2tf32(p);
                }
            }
            sum += __shfl_xor_sync(0xffffffffu, sum, 1);
            sum += __shfl_xor_sync(0xffffffffu, sum, 2);
            lt[s] = sum;
        }
        if (tg == 0) {
#pragma unroll
            for (int s = 0; s < 4; s++) {
                int row = wr * 32 + (s >> 1) * 16 + gp + (s & 1) * 8;
                lpart[wc * 128 + row] = lt[s];
            }
        }
#pragma unroll
        for (int s = 0; s < 4; s++) {
            int i = s >> 1, hh = s & 1;
            float f = fac[wr * 32 + i * 16 + gp + hh * 8];
#pragma unroll
            for (int j = 0; j < 4; j++) {
                accO[i][j][hh * 2] *= f;
                accO[i][j][hh * 2 + 1] *= f;
            }
        }
        __syncthreads();
        if (tid < 128) lrun[tid] = lrun[tid] * fac[tid] + lpart[tid] + lpart[128 + tid];

#pragma unroll
        for (int kt = 0; kt < 8; kt++) {
            const float* sa = Ps + kt * 2336;
            const float* sb = Vs + kt * 1168;
#pragma unroll
            for (int ks = 0; ks < 2; ks++) {
                float4 af0 = *reinterpret_cast<const float4*>(sa + aR + ks * 136);
                float4 af1 = *reinterpret_cast<const float4*>(sa + aR + 292 + ks * 136);
#pragma unroll
                for (int p = 0; p < 2; p++) {
                    float4 bf = *reinterpret_cast<const float4*>(sb + bRo + p * 292 + ks * 136);
                    mma4(accO[0][2 * p    ], reinterpret_cast<const float*>(&af0), bf.x, bf.y);
                    mma4(accO[1][2 * p    ], reinterpret_cast<const float*>(&af1), bf.x, bf.y);
                    mma4(accO[0][2 * p + 1], reinterpret_cast<const float*>(&af0), bf.z, bf.w);
                    mma4(accO[1][2 * p + 1], reinterpret_cast<const float*>(&af1), bf.z, bf.w);
                }
            }
        }
    }
    __syncthreads();

#pragma unroll
    for (int i = 0; i < 2; i++)
#pragma unroll
        for (int j = 0; j < 4; j++)
#pragma unroll
            for (int qq = 0; qq < 4; qq++) {
                int row = wr * 32 + i * 16 + gp + (qq >> 1) * 8;
                int gr = qb * 128 + row;
                if (gr >= HW) continue;
                int col = wc * 32 + j * 8 + tg * 2 + (qq & 1);
                ao[((size_t)b * HW + gr) * CCH + h * 64 + col] =
                    accO[i][j][qq] / lrun[row];
            }
}

// ======= SIMT tf32 MMA GEMM: KT32 buffers, 1 barrier / 32-k =========
template<bool TB, int NT>
__global__ __launch_bounds__(256, 2)
void mma_gemm_kernel(const float* __restrict__ A, const float* __restrict__ Bm,
                     const float* __restrict__ bias, const float* __restrict__ res,
                     float* __restrict__ C,
                     int M, int N, int K, int lda, int ldb, int ldc,
                     long long sAo, long long sAi, long long sBo, long long sBi,
                     long long sCo, long long sCi, int inner, float alpha,
                     int fuseGeglu) {
    constexpr int NPW = NT / 32;
    constexpr int NJ  = NT / 16;
    constexpr int CHA = 8 * 292;             // 2336 (A 16-k chunk)
    constexpr int CHB = (NT / 16) * 292;     // B 16-k chunk
    constexpr int ABUF = 2 * CHA;            // 32-k buffer
    constexpr int BBUF = 2 * CHB;
    constexpr int NB4 = NT / 64;

    int z = blockIdx.z;
    int zo = z / inner, zi = z % inner;
    A  += (size_t)(zo * sAo + zi * sAi);
    Bm += (size_t)(zo * sBo + zi * sBi);
    long long coff = zo * sCo + zi * sCi;
    C += coff;
    if (res) res += coff;

    extern __shared__ __align__(16) float DSM[];
    float* SA = DSM;
    float* SB = DSM + 2 * ABUF;

    const int tid = threadIdx.x, wid = tid >> 5, lane = tid & 31;
    const int wr = wid >> 1, wc = wid & 1, gp = lane >> 2, tg = lane & 3;
    const int fl = (lane ^ (lane >> 3)) * 4;
    const int mBase = blockIdx.y * 128, nBase = blockIdx.x * NT;

    const float4* pA[2];
    int baseA[2], cA[2];
#pragma unroll
    for (int u = 0; u < 2; u++) {
        int e = u * 256 + tid;
        int row = e >> 2, kq = e & 3;
        int gm = mBase + row;
        if (gm >= M) gm = 0;
        pA[u] = reinterpret_cast<const float4*>(A + (size_t)gm * lda) + kq;
        cA[u] = (row >> 1) & 3;
        baseA[u] = offAe(row, kq * 4) - (cA[u] << 2);
    }
    const float4* pB[NB4];
    int baseB[NB4][4];
#pragma unroll
    for (int u = 0; u < NB4; u++) {
        int e = u * 256 + tid;
        if (TB) {
            int n = e >> 2, kq = e & 3;
            int gn = nBase + n;
            if (gn >= N) gn = 0;
            pB[u] = reinterpret_cast<const float4*>(Bm + (size_t)gn * ldb) + kq;
            int c = (n >> 1) & 3;
            baseB[u][0] = offBe(n, kq * 4) - (c << 2);
            baseB[u][1] = c;
        } else {
            int k, nq;
            if (NT == 128) { k = e >> 5; nq = e & 31; }
            else           { k = e >> 4; nq = e & 15; }
            pB[u] = reinterpret_cast<const float4*>(Bm + (size_t)k * ldb + nBase) + nq;
#pragma unroll
            for (int i = 0; i < 4; i++)
                baseB[u][i] = offBe(4 * nq + i, k);
        }
    }
    const long long stepB = TB ? 4LL : 4LL * (long long)ldb;   // one 16-k chunk

    float acc[2][NJ][4];
#pragma unroll
    for (int i = 0; i < 2; i++)
#pragma unroll
        for (int j = 0; j < NJ; j++)
#pragma unroll
            for (int q = 0; q < 4; q++) acc[i][j][q] = 0.f;

    float4 va[2], vb[NB4];
    auto loadChunk = [&]() {
#pragma unroll
        for (int u = 0; u < 2; u++) { va[u] = *pA[u]; pA[u] += 4; }
#pragma unroll
        for (int u = 0; u < NB4; u++) { vb[u] = *pB[u]; pB[u] += stepB; }
    };
    auto storeChunk = [&](int bf, int ch) {
        float* sa = SA + bf * ABUF + ch * CHA;
        float* sbu = SB + bf * BBUF + ch * CHB;
#pragma unroll
        for (int u = 0; u < 2; u++) {
            int c = cA[u];
            sa[baseA[u] + ((0 ^ c) << 2)] = f2tf32(va[u].x);
            sa[baseA[u] + ((1 ^ c) << 2)] = f2tf32(va[u].y);
            sa[baseA[u] + ((2 ^ c) << 2)] = f2tf32(va[u].z);
            sa[baseA[u] + ((3 ^ c) << 2)] = f2tf32(va[u].w);
        }
#pragma unroll
        for (int u = 0; u < NB4; u++) {
            if (TB) {
                int c = baseB[u][1], bb = baseB[u][0];
                sbu[bb + ((0 ^ c) << 2)] = f2tf32(vb[u].x);
                sbu[bb + ((1 ^ c) << 2)] = f2tf32(vb[u].y);
                sbu[bb + ((2 ^ c) << 2)] = f2tf32(vb[u].z);
                sbu[bb + ((3 ^ c) << 2)] = f2tf32(vb[u].w);
            } else {
                sbu[baseB[u][0]] = f2tf32(vb[u].x);
                sbu[baseB[u][1]] = f2tf32(vb[u].y);
                sbu[baseB[u][2]] = f2tf32(vb[u].z);
                sbu[baseB[u][3]] = f2tf32(vb[u].w);
            }
        }
    };

    const int aR = wr * 2 * 292 + fl;
    const int bR = wc * NPW * 292 + fl;
    auto compute = [&](const float* sa, const float* sbu) {
#pragma unroll
        for (int ks = 0; ks < 2; ks++) {
            float4 af0 = *reinterpret_cast<const float4*>(sa + aR + ks * 136);
            float4 af1 = *reinterpret_cast<const float4*>(sa + aR + 292 + ks * 136);
#pragma unroll
            for (int p = 0; p < NPW; p++) {
                float4 bf = *reinterpret_cast<const float4*>(sbu + bR + p * 292 + ks * 136);
                mma4(acc[0][2 * p    ], reinterpret_cast<const float*>(&af0), bf.x, bf.y);
                mma4(acc[1][2 * p    ], reinterpret_cast<const float*>(&af1), bf.x, bf.y);
                mma4(acc[0][2 * p + 1], reinterpret_cast<const float*>(&af0), bf.z, bf.w);
                mma4(acc[1][2 * p + 1], reinterpret_cast<const float*>(&af1), bf.z, bf.w);
            }
        }
    };

    // prologue: fill buffer 0 (two chunks)
    loadChunk(); storeChunk(0, 0);
    loadChunk(); storeChunk(0, 1);
    __syncthreads();

    const int nIter = K >> 5;
    for (int kt = 0; kt < nIter; kt++) {
        const float* sa = SA + (kt & 1) * ABUF;
        const float* sbu = SB + (kt & 1) * BBUF;
        const int nb = (kt + 1) & 1;
        bool more = (kt + 1 < nIter);
        if (more) loadChunk();
        compute(sa, sbu);
        if (more) { storeChunk(nb, 0); loadChunk(); }
        compute(sa + CHA, sbu + CHB);
        if (more) storeChunk(nb, 1);
        __syncthreads();
    }

    if (fuseGeglu) {
#pragma unroll
        for (int i = 0; i < 2; i++) {
#pragma unroll
            for (int j = 0; j < NJ; j++) {
                int r0 = mBase + wr * 32 + i * 16 + gp;
                int c0 = nBase + wc * (NT / 2) + j * 8 + tg * 2;
#pragma unroll
                for (int h = 0; h < 2; h++) {
                    int row = r0 + h * 8;
                    if (row >= M) continue;
                    float a = acc[i][j][h * 2 + 0] + bias[c0];
                    float g = acc[i][j][h * 2 + 1] + bias[c0 + 1];
                    float gelu = 0.5f * g * (1.f + erff(g * 0.70710678118654752f));
                    C[(size_t)row * ldc + (c0 >> 1)] = a * gelu;
                }
            }
        }
        return;
    }

    const bool evenLdc = ((ldc & 1) == 0);
#pragma unroll
    for (int i = 0; i < 2; i++) {
#pragma unroll
        for (int j = 0; j < NJ; j++) {
            int r0 = mBase + wr * 32 + i * 16 + gp;
            int c0 = nBase + wc * (NT / 2) + j * 8 + tg * 2;
#pragma unroll
            for (int h = 0; h < 2; h++) {
                int row = r0 + h * 8;
                if (row >= M) continue;
                float v0 = acc[i][j][h * 2 + 0] * alpha;
                float v1 = acc[i][j][h * 2 + 1] * alpha;
                if (evenLdc && c0 + 1 < N) {
                    if (bias) { v0 += bias[c0]; v1 += bias[c0 + 1]; }
                    if (res) {
                        const float2 rr = *reinterpret_cast<const float2*>(&res[(size_t)row * ldc + c0]);
                        v0 += rr.x; v1 += rr.y;
                    }
                    float2 o; o.x = v0; o.y = v1;
                    *reinterpret_cast<float2*>(&C[(size_t)row * ldc + c0]) = o;
                } else {
                    if (c0 < N) {
                        if (bias) v0 += bias[c0];
                        if (res)  v0 += res[(size_t)row * ldc + c0];
                        C[(size_t)row * ldc + c0] = v0;
                    }
                    if (c0 + 1 < N) {
                        if (bias) v1 += bias[c0 + 1];
                        if (res)  v1 += res[(size_t)row * ldc + c0 + 1];
                        C[(size_t)row * ldc + c0 + 1] = v1;
                    }
                }
            }
        }
    }
}

__global__ void reduce4_kernel(const float* __restrict__ p, const float* __restrict__ bias,
                               const float* __restrict__ res, float* __restrict__ C,
                               int M, int N, int ldc) {
    size_t i4 = (size_t)blockIdx.x * blockDim.x + threadIdx.x;
    size_t MN4 = (size_t)M * N / 4;
    if (i4 >= MN4) return;
    size_t idx = i4 * 4;
    int row = (int)(idx / N), col = (int)(idx % N);
    const float4* p4 = reinterpret_cast<const float4*>(p);
    float4 a = p4[i4], b2 = p4[i4 + MN4], c2 = p4[i4 + 2 * MN4], d2 = p4[i4 + 3 * MN4];
    float4 v;
    v.x = a.x + b2.x + c2.x + d2.x;
    v.y = a.y + b2.y + c2.y + d2.y;
    v.z = a.z + b2.z + c2.z + d2.z;
    v.w = a.w + b2.w + c2.w + d2.w;
    if (bias) {
        const float4 bb = *reinterpret_cast<const float4*>(bias + col);
        v.x += bb.x; v.y += bb.y; v.z += bb.z; v.w += bb.w;
    }
    size_t o = (size_t)row * ldc + col;
    if (res) {
        const float4 rr = *reinterpret_cast<const float4*>(res + o);
        v.x += rr.x; v.y += rr.y; v.z += rr.z; v.w += rr.w;
    }
    *reinterpret_cast<float4*>(C + o) = v;
}

__global__ void reduce4_final_kernel(const float* __restrict__ p, const float* __restrict__ bias,
                                     const float* __restrict__ x, float* __restrict__ out) {
    size_t idx = (size_t)blockIdx.x * blockDim.x + threadIdx.x;
    size_t MN = (size_t)MTOK * CCH;
    if (idx >= MN) return;
    size_t row = idx / CCH, col = idx % CCH;
    float v = p[idx] + p[idx + MN] + p[idx + 2 * MN] + p[idx + 3 * MN] + bias[col];
    size_t b = row / HW, pix = row % HW;
    size_t o = (b * CCH + col) * HW + pix;
    out[o] = v + x[o];
}

__global__ void softmax_kernel(float* __restrict__ sc, int len, int ld, int pad) {
    __shared__ float rowbuf[HW];
    float* p = sc + (size_t)blockIdx.x * ld;
    float mx = -INFINITY;
    for (int i = threadIdx.x; i < len; i += blockDim.x) {
        float v = p[i]; rowbuf[i] = v; mx = fmaxf(mx, v);
    }
    mx = blockReduceMax(mx);
    float sum = 0.f;
    for (int i = threadIdx.x; i < len; i += blockDim.x) {
        float e = __expf(rowbuf[i] - mx); rowbuf[i] = e; sum += e;
    }
    sum = blockReduceSum(sum);
    float inv = 1.f / sum;
    for (int i = threadIdx.x; i < len; i += blockDim.x) p[i] = rowbuf[i] * inv;
    for (int i = len + threadIdx.x; i < pad; i += blockDim.x) p[i] = 0.f;
}

static int gemm_smem(int nt) {
    int cha = 8 * 292, chb = (nt / 16) * 292;
    return (4 * cha + 4 * chb) * 4;
}

static void launch_gemm(bool tb, int nt, const float* A, const float* B,
                        const float* bias, const float* res, float* C,
                        int M, int N, int K, int lda, int ldb, int ldc,
                        int batches, int inner,
                        long long sAo, long long sAi, long long sBo, long long sBi,
                        long long sCo, long long sCi, float alpha, int fuseGeglu = 0) {
    dim3 grid((N + nt - 1) / nt, (M + 127) / 128, batches);
    int sm = gemm_smem(nt);
    if (tb) {
        if (nt == 128)
            mma_gemm_kernel<true, 128><<<grid, 256, sm>>>(A, B, bias, res, C, M, N, K, lda, ldb, ldc,
                                                          sAo, sAi, sBo, sBi, sCo, sCi, inner, alpha, fuseGeglu);
        else
            mma_gemm_kernel<true, 64><<<grid, 256, sm>>>(A, B, bias, res, C, M, N, K, lda, ldb, ldc,
                                                         sAo, sAi, sBo, sBi, sCo, sCi, inner, alpha, fuseGeglu);
    } else {
        if (nt == 128)
            mma_gemm_kernel<false, 128><<<grid, 256, sm>>>(A, B, bias, res, C, M, N, K, lda, ldb, ldc,
                                                           sAo, sAi, sBo, sBi, sCo, sCi, inner, alpha, fuseGeglu);
        else
            mma_gemm_kernel<false, 64><<<grid, 256, sm>>>(A, B, bias, res, C, M, N, K, lda, ldb, ldc,
                                                          sAo, sAi, sBo, sBi, sCo, sCi, inner, alpha, fuseGeglu);
    }
}

static void launch_gemm_sk4(const float* A, const float* B, const float* bias,
                            const float* res, float* C, float* scratch,
                            int M, int N, int K, int lda, int ldb, int ldc) {
    int kLen = K / 4;
    launch_gemm(false, 128, A, B, nullptr, nullptr, scratch, M, N, kLen,
                lda, ldb, N, 4, 1,
                kLen, 0, (long long)kLen * ldb, 0, (long long)M * N, 0, 1.f);
    size_t MN4 = (size_t)M * N / 4;
    reduce4_kernel<<<(int)((MN4 + 255) / 256), 256>>>(scratch, bias, res, C, M, N, ldc);
}

static void launch_gemm_sk4_ln(const float* A, const float* B, const float* bias,
                               const float* res, float* tOut, float* scratch,
                               const float* s, const float* bln, float* nOut,
                               int K, int lda, int ldb) {
    int kLen = K / 4;
    launch_gemm(false, 128, A, B, nullptr, nullptr, scratch, MTOK, CCH, kLen,
                lda, ldb, CCH, 4, 1,
                kLen, 0, (long long)kLen * ldb, 0, (long long)MTOK * CCH, 0, 1.f);
    reduce4_ln_kernel<<<MTOK, 256>>>(scratch, bias, res, tOut, s, bln, nOut);
}

extern "C" void kernel_launch(void* const* d_in, const int* in_sizes, int n_in,
                              void* d_out, int out_size) {
    const float* x      = (const float*)d_in[0];
    const float* ctx    = (const float*)d_in[1];
    const float* gn_s   = (const float*)d_in[2];
    const float* gn_b   = (const float*)d_in[3];
    const float* pin_w  = (const float*)d_in[4];
    const float* pin_b  = (const float*)d_in[5];
    const float* ln1_s  = (const float*)d_in[6];
    const float* ln1_b  = (const float*)d_in[7];
    const float* wq1    = (const float*)d_in[8];
    const float* wk1    = (const float*)d_in[9];
    const float* wv1    = (const float*)d_in[10];
    const float* wo1    = (const float*)d_in[11];
    const float* bo1    = (const float*)d_in[12];
    const float* ln2_s  = (const float*)d_in[13];
    const float* ln2_b  = (const float*)d_in[14];
    const float* wq2    = (const float*)d_in[15];
    const float* wk2    = (const float*)d_in[16];
    const float* wv2    = (const float*)d_in[17];
    const float* wo2    = (const float*)d_in[18];
    const float* bo2    = (const float*)d_in[19];
    const float* ln3_s  = (const float*)d_in[20];
    const float* ln3_b  = (const float*)d_in[21];
    const float* ff_w1  = (const float*)d_in[22];
    const float* ff_b1  = (const float*)d_in[23];
    const float* ff_w2  = (const float*)d_in[24];
    const float* ff_b2  = (const float*)d_in[25];
    const float* pout_w = (const float*)d_in[26];
    const float* pout_b = (const float*)d_in[27];
    float* out = (float*)d_out;

    float *t, *tmp, *qkv, *ao, *scores, *ffh, *ffa, *w3, *w2c, *w1i, *b1i;
    cudaGetSymbolAddress((void**)&t,      g_t);
    cudaGetSymbolAddress((void**)&tmp,    g_tmp);
    cudaGetSymbolAddress((void**)&qkv,    g_qkv);
    cudaGetSymbolAddress((void**)&ao,     g_ao);
    cudaGetSymbolAddress((void**)&scores, g_scores);
    cudaGetSymbolAddress((void**)&ffh,    g_ffh);
    cudaGetSymbolAddress((void**)&ffa,    g_ffa);
    cudaGetSymbolAddress((void**)&w3,     g_w3);
    cudaGetSymbolAddress((void**)&w2c,    g_w2c);
    cudaGetSymbolAddress((void**)&w1i,    g_w1i);
    cudaGetSymbolAddress((void**)&b1i,    g_b1i);

    cudaFuncSetAttribute(flash_kernel, cudaFuncAttributeMaxDynamicSharedMemorySize,
                         FA_SMEM_BYTES);
    cudaFuncSetAttribute(mma_gemm_kernel<false, 128>,
                         cudaFuncAttributeMaxDynamicSharedMemorySize, gemm_smem(128));
    cudaFuncSetAttribute(mma_gemm_kernel<false, 64>,
                         cudaFuncAttributeMaxDynamicSharedMemorySize, gemm_smem(64));
    cudaFuncSetAttribute(mma_gemm_kernel<true, 64>,
                         cudaFuncAttributeMaxDynamicSharedMemorySize, gemm_smem(64));

    const float attn_scale = 0.125f;
    const int LD3 = 3 * CCH, LD2 = 2 * CCH;

    cudaMemcpy2DAsync(w3,         LD3 * 4, wq1, CCH * 4, CCH * 4, CCH, cudaMemcpyDeviceToDevice);
    cudaMemcpy2DAsync(w3 + CCH,   LD3 * 4, wk1, CCH * 4, CCH * 4, CCH, cudaMemcpyDeviceToDevice);
    cudaMemcpy2DAsync(w3 + 2*CCH, LD3 * 4, wv1, CCH * 4, CCH * 4, CCH, cudaMemcpyDeviceToDevice);
    cudaMemcpy2DAsync(w2c,        LD2 * 4, wk2, CCH * 4, CCH * 4, CCH, cudaMemcpyDeviceToDevice);
    cudaMemcpy2DAsync(w2c + CCH,  LD2 * 4, wv2, CCH * 4, CCH * 4, CCH, cudaMemcpyDeviceToDevice);
    {
        size_t total = (size_t)CCH * FFD;
        prep_w1_kernel<<<(int)((total + 255) / 256), 256>>>(ff_w1, ff_b1, w1i, b1i);
    }

    groupnorm_kernel<<<BATCH * GN_GROUPS, 256>>>(x, gn_s, gn_b, tmp);
    launch_gemm_sk4_ln(tmp, pin_w, pin_b, nullptr, t, ffh, ln1_s, ln1_b, tmp, CCH, CCH, CCH);

    // ---- self-attention (flash) ----
    launch_gemm(false, 128, tmp, w3, nullptr, nullptr, qkv, MTOK, 3 * CCH, CCH,
                CCH, LD3, LD3, 1, 1, 0, 0, 0, 0, 0, 0, 1.f);
    {
        dim3 gf(1, 13, BATCH * HEADS);
        flash_kernel<<<gf, 256, FA_SMEM_BYTES>>>(qkv, ao);
    }
    launch_gemm_sk4_ln(ao, wo1, bo1, t, t, ffh, ln2_s, ln2_b, tmp, CCH, CCH, CCH);

    // ---- cross-attention (scores ld = CTXP = 96) ----
    launch_gemm_sk4(tmp, wq2, nullptr, nullptr, qkv, ffh, MTOK, CCH, CCH, CCH, CCH, LD3);
    launch_gemm(false, 128, ctx, w2c, nullptr, nullptr, qkv + CCH, BATCH * CTXL, 2 * CCH, CCH,
                CCH, LD2, LD3, 1, 1, 0, 0, 0, 0, 0, 0, 1.f);
    launch_gemm(true, 64, qkv, qkv + CCH, nullptr, nullptr, scores, HW, CTXL, DH,
                LD3, LD3, CTXP, BATCH * HEADS, HEADS,
                (long long)HW * LD3, DH, (long long)CTXL * LD3, DH,
                (long long)HEADS * HW * CTXP, (long long)HW * CTXP, attn_scale);
    softmax_kernel<<<BATCH * HEADS * HW, 256>>>(scores, CTXL, CTXP, CTXP);
    // K = CTXP = 96 (pad cols are exact zeros -> extra V rows inert)
    launch_gemm(false, 64, scores, qkv + 2 * CCH, nullptr, nullptr, ao, HW, DH, CTXP,
                CTXP, LD3, CCH, BATCH * HEADS, HEADS,
                (long long)HEADS * HW * CTXP, (long long)HW * CTXP,
                (long long)CTXL * LD3, DH, (long long)HW * CCH, DH, 1.f);
    launch_gemm_sk4_ln(ao, wo2, bo2, t, t, ffh, ln3_s, ln3_b, tmp, CCH, CCH, CCH);

    // ---- GEGLU FF (ff1 fused geglu) ----
    launch_gemm(false, 128, tmp, w1i, b1i, nullptr, ffa, MTOK, 2 * FFD, CCH,
                CCH, 2 * FFD, FFD, 1, 1, 0, 0, 0, 0, 0, 0, 1.f, 1);
    launch_gemm_sk4(ffa, ff_w2, ff_b2, t, t, ffh, MTOK, CCH, FFD, FFD, CCH, CCH);

    // ---- proj_out (split-K4, fused reduce+transpose+residual) ----
    {
        int kLen = CCH / 4;
        launch_gemm(false, 128, t, pout_w, nullptr, nullptr, ffh, MTOK, CCH, kLen,
                    CCH, CCH, CCH, 4, 1,
                    kLen, 0, (long long)kLen * CCH, 0, (long long)MTOK * CCH, 0, 1.f);
        size_t MN = (size_t)MTOK * CCH;
        reduce4_final_kernel<<<(int)((MN + 255) / 256), 256>>>(ffh, pout_b, x, out);
    }
}

// round 17
// speedup vs baseline: 1.0426x; 1.0426x over previous
#include <cuda_runtime.h>
#include <math.h>
#include <stdint.h>

#define BATCH   2
#define CCH     1024
#define HW      1600
#define MTOK    (BATCH*HW)
#define HEADS   16
#define DH      64
#define CTXL    77
#define CTXP    80
#define FFD     4096
#define GN_GROUPS 32
#define GN_EPS  1e-6f
#define LN_EPS  1e-5f

__device__ float g_t   [MTOK * CCH];
__device__ float g_tmp [MTOK * CCH];
__device__ float g_qkv [MTOK * 3 * CCH];
__device__ float g_ao  [MTOK * CCH];
__device__ float g_scores[(size_t)BATCH * HEADS * HW * CTXP];
__device__ float g_ffh [MTOK * 2 * FFD];
__device__ float g_ffa [MTOK * FFD];
__device__ float g_w3  [CCH * 3 * CCH];
__device__ float g_w2c [CCH * 2 * CCH];
__device__ float g_w1i [CCH * 2 * FFD];
__device__ float g_b1i [2 * FFD];

__device__ __forceinline__ float blockReduceSum(float v) {
    __shared__ float sh[32];
    int lane = threadIdx.x & 31, wid = threadIdx.x >> 5;
#pragma unroll
    for (int o = 16; o > 0; o >>= 1) v += __shfl_down_sync(0xffffffffu, v, o);
    if (lane == 0) sh[wid] = v;
    __syncthreads();
    int nw = (blockDim.x + 31) >> 5;
    v = (threadIdx.x < nw) ? sh[threadIdx.x] : 0.f;
    if (wid == 0) {
#pragma unroll
        for (int o = 16; o > 0; o >>= 1) v += __shfl_down_sync(0xffffffffu, v, o);
        if (lane == 0) sh[0] = v;
    }
    __syncthreads();
    float r = sh[0];
    __syncthreads();
    return r;
}

__global__ void groupnorm_kernel(const float* __restrict__ x, const float* __restrict__ s,
                                 const float* __restrict__ bgn, float* __restrict__ out) {
    int b = blockIdx.x / GN_GROUPS;
    int g = blockIdx.x % GN_GROUPS;
    const int CPG = CCH / GN_GROUPS, NEL = CPG * HW;
    const float* xp = x + ((size_t)b * CCH + (size_t)g * CPG) * HW;
    float sum = 0.f, sq = 0.f;
    for (int i = threadIdx.x; i < NEL; i += blockDim.x) {
        float v = xp[i]; sum += v; sq += v * v;
    }
    sum = blockReduceSum(sum); sq = blockReduceSum(sq);
    float mean = sum / (float)NEL;
    float inv = rsqrtf(sq / (float)NEL - mean * mean + GN_EPS);
    for (int i = threadIdx.x; i < NEL; i += blockDim.x) {
        int ci = i / HW, p = i % HW, c = g * CPG + ci;
        out[((size_t)b * HW + p) * CCH + c] = (xp[i] - mean) * inv * s[c] + bgn[c];
    }
}

// fused: y = sum4(p)(+bias)(+res) -> tOut; layernorm(y) -> nOut
__global__ void reduce4_ln_kernel(const float* __restrict__ p, const float* __restrict__ bias,
                                  const float* __restrict__ res, float* __restrict__ tOut,
                                  const float* __restrict__ s, const float* __restrict__ bln,
                                  float* __restrict__ nOut) {
    int row = blockIdx.x;
    const size_t MN = (size_t)MTOK * CCH;
    const int tid = threadIdx.x;
    const size_t base = (size_t)row * CCH + tid * 4;
    float4 a = *reinterpret_cast<const float4*>(p + base);
    float4 b2 = *reinterpret_cast<const float4*>(p + base + MN);
    float4 c2 = *reinterpret_cast<const float4*>(p + base + 2 * MN);
    float4 d2 = *reinterpret_cast<const float4*>(p + base + 3 * MN);
    float4 y;
    y.x = a.x + b2.x + c2.x + d2.x;
    y.y = a.y + b2.y + c2.y + d2.y;
    y.z = a.z + b2.z + c2.z + d2.z;
    y.w = a.w + b2.w + c2.w + d2.w;
    if (bias) {
        const float4 bb = *reinterpret_cast<const float4*>(bias + tid * 4);
        y.x += bb.x; y.y += bb.y; y.z += bb.z; y.w += bb.w;
    }
    if (res) {
        const float4 rr = *reinterpret_cast<const float4*>(res + base);
        y.x += rr.x; y.y += rr.y; y.z += rr.z; y.w += rr.w;
    }
    *reinterpret_cast<float4*>(tOut + base) = y;
    float sum = y.x + y.y + y.z + y.w;
    float sq = y.x * y.x + y.y * y.y + y.z * y.z + y.w * y.w;
    sum = blockReduceSum(sum); sq = blockReduceSum(sq);
    float mean = sum / (float)CCH;
    float inv = rsqrtf(sq / (float)CCH - mean * mean + LN_EPS);
    const float4 ss = *reinterpret_cast<const float4*>(s + tid * 4);
    const float4 lb = *reinterpret_cast<const float4*>(bln + tid * 4);
    float4 o;
    o.x = (y.x - mean) * inv * ss.x + lb.x;
    o.y = (y.y - mean) * inv * ss.y + lb.y;
    o.z = (y.z - mean) * inv * ss.z + lb.z;
    o.w = (y.w - mean) * inv * ss.w + lb.w;
    *reinterpret_cast<float4*>(nOut + base) = o;
}

__global__ void prep_w1_kernel(const float* __restrict__ w1, const float* __restrict__ b1,
                               float* __restrict__ w1i, float* __restrict__ b1i) {
    size_t idx = (size_t)blockIdx.x * blockDim.x + threadIdx.x;
    size_t total = (size_t)CCH * FFD;
    if (idx >= total) return;
    size_t k = idx / FFD, j = idx % FFD;
    w1i[k * 2 * FFD + 2 * j    ] = w1[k * 2 * FFD + j];
    w1i[k * 2 * FFD + 2 * j + 1] = w1[k * 2 * FFD + FFD + j];
    if (k == 0) {
        b1i[2 * j    ] = b1[j];
        b1i[2 * j + 1] = b1[FFD + j];
    }
}

__device__ __forceinline__ float f2tf32(float x) {
    uint32_t u;
    asm("cvt.rna.tf32.f32 %0, %1;" : "=r"(u) : "f"(x));
    return __uint_as_float(u);
}

__device__ __forceinline__ void mma4(float c[4], const float a[4], float b0, float b1) {
    asm volatile(
        "mma.sync.aligned.m16n8k8.row.col.f32.tf32.tf32.f32 "
        "{%0,%1,%2,%3}, {%4,%5,%6,%7}, {%8,%9}, {%0,%1,%2,%3};"
        : "+f"(c[0]), "+f"(c[1]), "+f"(c[2]), "+f"(c[3])
        : "r"(__float_as_uint(a[0])), "r"(__float_as_uint(a[1])),
          "r"(__float_as_uint(a[2])), "r"(__float_as_uint(a[3])),
          "r"(__float_as_uint(b0)), "r"(__float_as_uint(b1)));
}

__device__ __forceinline__ int offAe(int row, int k, int chstr) {
    int L = ((row & 7) << 2) | (k & 3);
    int g2 = L ^ (L >> 3);
    return (k >> 4) * chstr + (row >> 4) * 292 + ((k >> 3) & 1) * 136 + g2 * 4 +
           ((row >> 3) & 1) + (((k >> 2) & 1) << 1);
}
__device__ __forceinline__ int offBe(int n, int k, int chstr) {
    int L = ((n & 7) << 2) | (k & 3);
    int g2 = L ^ (L >> 3);
    return (k >> 4) * chstr + (n >> 4) * 292 + ((k >> 3) & 1) * 136 + g2 * 4 +
           (((n >> 3) & 1) << 1) + ((k >> 2) & 1);
}

// ================= flash attention (verified round 12) ==========
#define FA_Q  0
#define FA_K  9344
#define FA_V  18688
#define FA_P  28032
#define FA_ST 46720
#define FA_SMEM_BYTES ((46720 + 896) * 4)

__global__ __launch_bounds__(256)
void flash_kernel(const float* __restrict__ qkv, float* __restrict__ ao) {
    extern __shared__ float S[];
    float* Qs = S + FA_Q;
    float* Ks = S + FA_K;
    float* Vs = S + FA_V;
    float* Ps = S + FA_P;
    float* mpart = S + FA_ST;
    float* lpart = mpart + 256;
    float* mrun  = lpart + 256;
    float* fac   = mrun + 128;
    float* lrun  = fac + 128;

    const int tid = threadIdx.x, wid = tid >> 5, lane = tid & 31;
    const int wr = wid >> 1, wc = wid & 1, gp = lane >> 2, tg = lane & 3;
    const int fl = (lane ^ (lane >> 3)) * 4;
    const int qb = blockIdx.y;
    const int bh = blockIdx.z;
    const int b = bh >> 4, h = bh & 15;
    const size_t bhbase = (size_t)b * HW * 3072 + (size_t)h * 64;
    const float* Qg = qkv + bhbase;
    const float* Kg = qkv + CCH + bhbase;
    const float* Vg = qkv + 2 * CCH + bhbase;

#pragma unroll
    for (int u = 0; u < 8; u++) {
        int e = u * 256 + tid;
        int row = e >> 4, q4 = e & 15;
        int gr = qb * 128 + row;
        if (gr >= HW) gr = qb * 128;
        const float4 v = *(reinterpret_cast<const float4*>(Qg + (size_t)gr * 3072) + q4);
        int c = (row >> 1) & 3;
        int base = offAe(row, q4 * 4, 2336) - (c << 2);
        Qs[base + ((0 ^ c) << 2)] = f2tf32(v.x * 0.125f);
        Qs[base + ((1 ^ c) << 2)] = f2tf32(v.y * 0.125f);
        Qs[base + ((2 ^ c) << 2)] = f2tf32(v.z * 0.125f);
        Qs[base + ((3 ^ c) << 2)] = f2tf32(v.w * 0.125f);
    }
    if (tid < 128) { mrun[tid] = -INFINITY; lrun[tid] = 0.f; }

    float accO[2][4][4];
#pragma unroll
    for (int i = 0; i < 2; i++)
#pragma unroll
        for (int j = 0; j < 4; j++)
#pragma unroll
            for (int q = 0; q < 4; q++) accO[i][j][q] = 0.f;

    const int aR  = wr * 2 * 292 + fl;
    const int bRs = wc * 4 * 292 + fl;
    const int bRo = wc * 2 * 292 + fl;
    const int KVT = 13;

    for (int t = 0; t < KVT; t++) {
        __syncthreads();
#pragma unroll
        for (int u = 0; u < 8; u++) {
            int e = u * 256 + tid;
            int row = e >> 4, q4 = e & 15;
            int gr = t * 128 + row;
            if (gr >= HW) gr = t * 128;
            const float4 kv4 = *(reinterpret_cast<const float4*>(Kg + (size_t)gr * 3072) + q4);
            int c = (row >> 1) & 3;
            int kb = offBe(row, q4 * 4, 2336) - (c << 2);
            Ks[kb + ((0 ^ c) << 2)] = f2tf32(kv4.x);
            Ks[kb + ((1 ^ c) << 2)] = f2tf32(kv4.y);
            Ks[kb + ((2 ^ c) << 2)] = f2tf32(kv4.z);
            Ks[kb + ((3 ^ c) << 2)] = f2tf32(kv4.w);
            const float4 vv = *(reinterpret_cast<const float4*>(Vg + (size_t)gr * 3072) + q4);
            int n0 = q4 * 4;
            Vs[offBe(n0 + 0, row, 1168)] = f2tf32(vv.x);
            Vs[offBe(n0 + 1, row, 1168)] = f2tf32(vv.y);
            Vs[offBe(n0 + 2, row, 1168)] = f2tf32(vv.z);
            Vs[offBe(n0 + 3, row, 1168)] = f2tf32(vv.w);
        }
        __syncthreads();

        float acc[2][8][4];
#pragma unroll
        for (int i = 0; i < 2; i++)
#pragma unroll
            for (int j = 0; j < 8; j++)
#pragma unroll
                for (int q = 0; q < 4; q++) acc[i][j][q] = 0.f;
#pragma unroll
        for (int kt = 0; kt < 4; kt++) {
            const float* sa = Qs + kt * 2336;
            const float* sb = Ks + kt * 2336;
#pragma unroll
            for (int ks = 0; ks < 2; ks++) {
                float4 af0 = *reinterpret_cast<const float4*>(sa + aR + ks * 136);
                float4 af1 = *reinterpret_cast<const float4*>(sa + aR + 292 + ks * 136);
#pragma unroll
                for (int p = 0; p < 4; p++) {
                    float4 bf = *reinterpret_cast<const float4*>(sb + bRs + p * 292 + ks * 136);
                    mma4(acc[0][2 * p    ], reinterpret_cast<const float*>(&af0), bf.x, bf.y);
                    mma4(acc[1][2 * p    ], reinterpret_cast<const float*>(&af1), bf.x, bf.y);
                    mma4(acc[0][2 * p + 1], reinterpret_cast<const float*>(&af0), bf.z, bf.w);
                    mma4(acc[1][2 * p + 1], reinterpret_cast<const float*>(&af1), bf.z, bf.w);
                }
            }
        }

        const bool maskw = (t == KVT - 1) && (wc == 1);

        float mt[4];
#pragma unroll
        for (int s = 0; s < 4; s++) {
            int i = s >> 1, hh = s & 1;
            float m = -INFINITY;
            if (!maskw) {
#pragma unroll
                for (int j = 0; j < 8; j++)
                    m = fmaxf(m, fmaxf(acc[i][j][hh * 2], acc[i][j][hh * 2 + 1]));
            }
            m = fmaxf(m, __shfl_xor_sync(0xffffffffu, m, 1));
            m = fmaxf(m, __shfl_xor_sync(0xffffffffu, m, 2));
            mt[s] = m;
        }
        if (tg == 0) {
#pragma unroll
            for (int s = 0; s < 4; s++) {
                int row = wr * 32 + (s >> 1) * 16 + gp + (s & 1) * 8;
                mpart[wc * 128 + row] = mt[s];
            }
        }
        __syncthreads();
        if (tid < 128) {
            float mo = mrun[tid];
            float mn = fmaxf(mo, fmaxf(mpart[tid], mpart[128 + tid]));
            mrun[tid] = mn;
            fac[tid] = __expf(mo - mn);
        }
        __syncthreads();

        float lt[4];
#pragma unroll
        for (int s = 0; s < 4; s++) {
            int i = s >> 1, hh = s & 1;
            int row = wr * 32 + i * 16 + gp + hh * 8;
            float mn = mrun[row];
            float sum = 0.f;
#pragma unroll
            for (int j = 0; j < 8; j++) {
#pragma unroll
                for (int qq = 0; qq < 2; qq++) {
                    float p = maskw ? 0.f : __expf(acc[i][j][hh * 2 + qq] - mn);
                    sum += p;
                    int col = wc * 64 + j * 8 + tg * 2 + qq;
                    Ps[offAe(row, col, 2336)] = f2tf32(p);
                }
            }
            sum += __shfl_xor_sync(0xffffffffu, sum, 1);
            sum += __shfl_xor_sync(0xffffffffu, sum, 2);
            lt[s] = sum;
        }
        if (tg == 0) {
#pragma unroll
            for (int s = 0; s < 4; s++) {
                int row = wr * 32 + (s >> 1) * 16 + gp + (s & 1) * 8;
                lpart[wc * 128 + row] = lt[s];
            }
        }
#pragma unroll
        for (int s = 0; s < 4; s++) {
            int i = s >> 1, hh = s & 1;
            float f = fac[wr * 32 + i * 16 + gp + hh * 8];
#pragma unroll
            for (int j = 0; j < 4; j++) {
                accO[i][j][hh * 2] *= f;
                accO[i][j][hh * 2 + 1] *= f;
            }
        }
        __syncthreads();
        if (tid < 128) lrun[tid] = lrun[tid] * fac[tid] + lpart[tid] + lpart[128 + tid];

#pragma unroll
        for (int kt = 0; kt < 8; kt++) {
            const float* sa = Ps + kt * 2336;
            const float* sb = Vs + kt * 1168;
#pragma unroll
            for (int ks = 0; ks < 2; ks++) {
                float4 af0 = *reinterpret_cast<const float4*>(sa + aR + ks * 136);
                float4 af1 = *reinterpret_cast<const float4*>(sa + aR + 292 + ks * 136);
#pragma unroll
                for (int p = 0; p < 2; p++) {
                    float4 bf = *reinterpret_cast<const float4*>(sb + bRo + p * 292 + ks * 136);
                    mma4(accO[0][2 * p    ], reinterpret_cast<const float*>(&af0), bf.x, bf.y);
                    mma4(accO[1][2 * p    ], reinterpret_cast<const float*>(&af1), bf.x, bf.y);
                    mma4(accO[0][2 * p + 1], reinterpret_cast<const float*>(&af0), bf.z, bf.w);
                    mma4(accO[1][2 * p + 1], reinterpret_cast<const float*>(&af1), bf.z, bf.w);
                }
            }
        }
    }
    __syncthreads();

#pragma unroll
    for (int i = 0; i < 2; i++)
#pragma unroll
        for (int j = 0; j < 4; j++)
#pragma unroll
            for (int qq = 0; qq < 4; qq++) {
                int row = wr * 32 + i * 16 + gp + (qq >> 1) * 8;
                int gr = qb * 128 + row;
                if (gr >= HW) continue;
                int col = wc * 32 + j * 8 + tg * 2 + (qq & 1);
                ao[((size_t)b * HW + gr) * CCH + h * 64 + col] =
                    accO[i][j][qq] / lrun[row];
            }
}

// ======= SIMT tf32 MMA GEMM (round-15 verified; optional fused GEGLU) =======
template<bool TB, int NT>
__global__ __launch_bounds__(256, 2)
void mma_gemm_kernel(const float* __restrict__ A, const float* __restrict__ Bm,
                     const float* __restrict__ bias, const float* __restrict__ res,
                     float* __restrict__ C,
                     int M, int N, int K, int lda, int ldb, int ldc,
                     long long sAo, long long sAi, long long sBo, long long sBi,
                     long long sCo, long long sCi, int inner, float alpha,
                     int fuseGeglu) {
    constexpr int NPW = NT / 32;
    constexpr int NJ  = NT / 16;
    constexpr int ASZ = 8 * 292;
    constexpr int BSZ = (NT / 16) * 292;
    constexpr int NB4 = NT / 64;

    int z = blockIdx.z;
    int zo = z / inner, zi = z % inner;
    A  += (size_t)(zo * sAo + zi * sAi);
    Bm += (size_t)(zo * sBo + zi * sBi);
    long long coff = zo * sCo + zi * sCi;
    C += coff;
    if (res) res += coff;

    __shared__ __align__(16) float SA[2 * ASZ];
    __shared__ __align__(16) float SB[2 * BSZ];

    const int tid = threadIdx.x, wid = tid >> 5, lane = tid & 31;
    const int wr = wid >> 1, wc = wid & 1, gp = lane >> 2, tg = lane & 3;
    const int fl = (lane ^ (lane >> 3)) * 4;
    const int mBase = blockIdx.y * 128, nBase = blockIdx.x * NT;

    const float4* pA[2];
    int baseA[2], cA[2];
#pragma unroll
    for (int u = 0; u < 2; u++) {
        int e = u * 256 + tid;
        int row = e >> 2, kq = e & 3;
        int gm = mBase + row;
        if (gm >= M) gm = 0;
        pA[u] = reinterpret_cast<const float4*>(A + (size_t)gm * lda) + kq;
        cA[u] = (row >> 1) & 3;
        baseA[u] = offAe(row, kq * 4, ASZ) - (cA[u] << 2);
    }
    const float4* pB[NB4];
    int baseB[NB4][4];
#pragma unroll
    for (int u = 0; u < NB4; u++) {
        int e = u * 256 + tid;
        if (TB) {
            int n = e >> 2, kq = e & 3;
            int gn = nBase + n;
            if (gn >= N) gn = 0;
            pB[u] = reinterpret_cast<const float4*>(Bm + (size_t)gn * ldb) + kq;
            int c = (n >> 1) & 3;
            baseB[u][0] = offBe(n, kq * 4, BSZ) - (c << 2);
            baseB[u][1] = c;
        } else {
            int k, nq;
            if (NT == 128) { k = e >> 5; nq = e & 31; }
            else           { k = e >> 4; nq = e & 15; }
            pB[u] = reinterpret_cast<const float4*>(Bm + (size_t)k * ldb + nBase) + nq;
#pragma unroll
            for (int i = 0; i < 4; i++)
                baseB[u][i] = offBe(4 * nq + i, k, BSZ);
        }
    }
    const long long stepB = TB ? 4LL : 4LL * (long long)ldb;

    float acc[2][NJ][4];
#pragma unroll
    for (int i = 0; i < 2; i++)
#pragma unroll
        for (int j = 0; j < NJ; j++)
#pragma unroll
            for (int q = 0; q < 4; q++) acc[i][j][q] = 0.f;

    float4 va[2], vb[NB4];
    auto loadTile = [&]() {
#pragma unroll
        for (int u = 0; u < 2; u++) { va[u] = *pA[u]; pA[u] += 4; }
#pragma unroll
        for (int u = 0; u < NB4; u++) { vb[u] = *pB[u]; pB[u] += stepB; }
    };
    auto storeTile = [&](int bf) {
        float* sa = SA + bf * ASZ;
        float* sbu = SB + bf * BSZ;
#pragma unroll
        for (int u = 0; u < 2; u++) {
            int c = cA[u];
            sa[baseA[u] + ((0 ^ c) << 2)] = f2tf32(va[u].x);
            sa[baseA[u] + ((1 ^ c) << 2)] = f2tf32(va[u].y);
            sa[baseA[u] + ((2 ^ c) << 2)] = f2tf32(va[u].z);
            sa[baseA[u] + ((3 ^ c) << 2)] = f2tf32(va[u].w);
        }
#pragma unroll
        for (int u = 0; u < NB4; u++) {
            if (TB) {
                int c = baseB[u][1], bb = baseB[u][0];
                sbu[bb + ((0 ^ c) << 2)] = f2tf32(vb[u].x);
                sbu[bb + ((1 ^ c) << 2)] = f2tf32(vb[u].y);
                sbu[bb + ((2 ^ c) << 2)] = f2tf32(vb[u].z);
                sbu[bb + ((3 ^ c) << 2)] = f2tf32(vb[u].w);
            } else {
                sbu[baseB[u][0]] = f2tf32(vb[u].x);
                sbu[baseB[u][1]] = f2tf32(vb[u].y);
                sbu[baseB[u][2]] = f2tf32(vb[u].z);
                sbu[baseB[u][3]] = f2tf32(vb[u].w);
            }
        }
    };

    loadTile();
    storeTile(0);
    __syncthreads();

    const int ktiles = K >> 4;
    const int aR = wr * 2 * 292 + fl;
    const int bR = wc * NPW * 292 + fl;

    for (int kt = 0; kt < ktiles; kt++) {
        const float* sa = SA + (kt & 1) * ASZ;
        const float* sbu = SB + (kt & 1) * BSZ;
        bool more = (kt + 1 < ktiles);
        if (more) loadTile();
#pragma unroll
        for (int ks = 0; ks < 2; ks++) {
            float4 af0 = *reinterpret_cast<const float4*>(sa + aR + ks * 136);
            float4 af1 = *reinterpret_cast<const float4*>(sa + aR + 292 + ks * 136);
#pragma unroll
            for (int p = 0; p < NPW; p++) {
                float4 bf = *reinterpret_cast<const float4*>(sbu + bR + p * 292 + ks * 136);
                mma4(acc[0][2 * p    ], reinterpret_cast<const float*>(&af0), bf.x, bf.y);
                mma4(acc[1][2 * p    ], reinterpret_cast<const float*>(&af1), bf.x, bf.y);
                mma4(acc[0][2 * p + 1], reinterpret_cast<const float*>(&af0), bf.z, bf.w);
                mma4(acc[1][2 * p + 1], reinterpret_cast<const float*>(&af1), bf.z, bf.w);
            }
        }
        if (more) storeTile((kt + 1) & 1);
        __syncthreads();
    }

    if (fuseGeglu) {
#pragma unroll
        for (int i = 0; i < 2; i++) {
#pragma unroll
            for (int j = 0; j < NJ; j++) {
                int r0 = mBase + wr * 32 + i * 16 + gp;
                int c0 = nBase + wc * (NT / 2) + j * 8 + tg * 2;
#pragma unroll
                for (int h = 0; h < 2; h++) {
                    int row = r0 + h * 8;
                    if (row >= M) continue;
                    float a = acc[i][j][h * 2 + 0] + bias[c0];
                    float g = acc[i][j][h * 2 + 1] + bias[c0 + 1];
                    float gelu = 0.5f * g * (1.f + erff(g * 0.70710678118654752f));
                    C[(size_t)row * ldc + (c0 >> 1)] = a * gelu;
                }
            }
        }
        return;
    }

    const bool evenLdc = ((ldc & 1) == 0);
#pragma unroll
    for (int i = 0; i < 2; i++) {
#pragma unroll
        for (int j = 0; j < NJ; j++) {
            int r0 = mBase + wr * 32 + i * 16 + gp;
            int c0 = nBase + wc * (NT / 2) + j * 8 + tg * 2;
#pragma unroll
            for (int h = 0; h < 2; h++) {
                int row = r0 + h * 8;
                if (row >= M) continue;
                float v0 = acc[i][j][h * 2 + 0] * alpha;
                float v1 = acc[i][j][h * 2 + 1] * alpha;
                if (evenLdc && c0 + 1 < N) {
                    if (bias) { v0 += bias[c0]; v1 += bias[c0 + 1]; }
                    if (res) {
                        const float2 rr = *reinterpret_cast<const float2*>(&res[(size_t)row * ldc + c0]);
                        v0 += rr.x; v1 += rr.y;
                    }
                    float2 o; o.x = v0; o.y = v1;
                    *reinterpret_cast<float2*>(&C[(size_t)row * ldc + c0]) = o;
                } else {
                    if (c0 < N) {
                        if (bias) v0 += bias[c0];
                        if (res)  v0 += res[(size_t)row * ldc + c0];
                        C[(size_t)row * ldc + c0] = v0;
                    }
                    if (c0 + 1 < N) {
                        if (bias) v1 += bias[c0 + 1];
                        if (res)  v1 += res[(size_t)row * ldc + c0 + 1];
                        C[(size_t)row * ldc + c0 + 1] = v1;
                    }
                }
            }
        }
    }
}

__global__ void reduce4_kernel(const float* __restrict__ p, const float* __restrict__ bias,
                               const float* __restrict__ res, float* __restrict__ C,
                               int M, int N, int ldc) {
    size_t i4 = (size_t)blockIdx.x * blockDim.x + threadIdx.x;
    size_t MN4 = (size_t)M * N / 4;
    if (i4 >= MN4) return;
    size_t idx = i4 * 4;
    int row = (int)(idx / N), col = (int)(idx % N);
    const float4* p4 = reinterpret_cast<const float4*>(p);
    float4 a = p4[i4], b2 = p4[i4 + MN4], c2 = p4[i4 + 2 * MN4], d2 = p4[i4 + 3 * MN4];
    float4 v;
    v.x = a.x + b2.x + c2.x + d2.x;
    v.y = a.y + b2.y + c2.y + d2.y;
    v.z = a.z + b2.z + c2.z + d2.z;
    v.w = a.w + b2.w + c2.w + d2.w;
    if (bias) {
        const float4 bb = *reinterpret_cast<const float4*>(bias + col);
        v.x += bb.x; v.y += bb.y; v.z += bb.z; v.w += bb.w;
    }
    size_t o = (size_t)row * ldc + col;
    if (res) {
        const float4 rr = *reinterpret_cast<const float4*>(res + o);
        v.x += rr.x; v.y += rr.y; v.z += rr.z; v.w += rr.w;
    }
    *reinterpret_cast<float4*>(C + o) = v;
}

__global__ void reduce4_final_kernel(const float* __restrict__ p, const float* __restrict__ bias,
                                     const float* __restrict__ x, float* __restrict__ out) {
    size_t idx = (size_t)blockIdx.x * blockDim.x + threadIdx.x;
    size_t MN = (size_t)MTOK * CCH;
    if (idx >= MN) return;
    size_t row = idx / CCH, col = idx % CCH;
    float v = p[idx] + p[idx + MN] + p[idx + 2 * MN] + p[idx + 3 * MN] + bias[col];
    size_t b = row / HW, pix = row % HW;
    size_t o = (b * CCH + col) * HW + pix;
    out[o] = v + x[o];
}

// ---- warp-per-row softmax for cross-attn (len=77, ld=80) ----
__global__ void softmax_warp_kernel(float* __restrict__ sc) {
    const int nrows = BATCH * HEADS * HW;
    int row = blockIdx.x * 8 + (threadIdx.x >> 5);
    if (row >= nrows) return;
    int lane = threadIdx.x & 31;
    float* p = sc + (size_t)row * CTXP;
    float a0 = p[lane];
    float a1 = p[lane + 32];
    float a2 = (lane + 64 < CTXL) ? p[lane + 64] : -INFINITY;
    float mx = fmaxf(a0, fmaxf(a1, a2));
#pragma unroll
    for (int o = 16; o > 0; o >>= 1) mx = fmaxf(mx, __shfl_xor_sync(0xffffffffu, mx, o));
    float e0 = __expf(a0 - mx), e1 = __expf(a1 - mx);
    float e2 = (lane + 64 < CTXL) ? __expf(a2 - mx) : 0.f;
    float s = e0 + e1 + e2;
#pragma unroll
    for (int o = 16; o > 0; o >>= 1) s += __shfl_xor_sync(0xffffffffu, s, o);
    float inv = 1.f / s;
    p[lane] = e0 * inv;
    p[lane + 32] = e1 * inv;
    if (lane + 64 < CTXP) p[lane + 64] = (lane + 64 < CTXL) ? e2 * inv : 0.f;
}

static void launch_gemm(bool tb, int nt, const float* A, const float* B,
                        const float* bias, const float* res, float* C,
                        int M, int N, int K, int lda, int ldb, int ldc,
                        int batches, int inner,
                        long long sAo, long long sAi, long long sBo, long long sBi,
                        long long sCo, long long sCi, float alpha, int fuseGeglu = 0) {
    dim3 grid((N + nt - 1) / nt, (M + 127) / 128, batches);
    if (tb) {
        if (nt == 128)
            mma_gemm_kernel<true, 128><<<grid, 256>>>(A, B, bias, res, C, M, N, K, lda, ldb, ldc,
                                                      sAo, sAi, sBo, sBi, sCo, sCi, inner, alpha, fuseGeglu);
        else
            mma_gemm_kernel<true, 64><<<grid, 256>>>(A, B, bias, res, C, M, N, K, lda, ldb, ldc,
                                                     sAo, sAi, sBo, sBi, sCo, sCi, inner, alpha, fuseGeglu);
    } else {
        if (nt == 128)
            mma_gemm_kernel<false, 128><<<grid, 256>>>(A, B, bias, res, C, M, N, K, lda, ldb, ldc,
                                                       sAo, sAi, sBo, sBi, sCo, sCi, inner, alpha, fuseGeglu);
        else
            mma_gemm_kernel<false, 64><<<grid, 256>>>(A, B, bias, res, C, M, N, K, lda, ldb, ldc,
                                                      sAo, sAi, sBo, sBi, sCo, sCi, inner, alpha, fuseGeglu);
    }
}

static void launch_gemm_sk4(const float* A, const float* B, const float* bias,
                            const float* res, float* C, float* scratch,
                            int M, int N, int K, int lda, int ldb, int ldc) {
    int kLen = K / 4;
    launch_gemm(false, 128, A, B, nullptr, nullptr, scratch, M, N, kLen,
                lda, ldb, N, 4, 1,
                kLen, 0, (long long)kLen * ldb, 0, (long long)M * N, 0, 1.f);
    size_t MN4 = (size_t)M * N / 4;
    reduce4_kernel<<<(int)((MN4 + 255) / 256), 256>>>(scratch, bias, res, C, M, N, ldc);
}

static void launch_gemm_sk4_ln(const float* A, const float* B, const float* bias,
                               const float* res, float* tOut, float* scratch,
                               const float* s, const float* bln, float* nOut,
                               int K, int lda, int ldb) {
    int kLen = K / 4;
    launch_gemm(false, 128, A, B, nullptr, nullptr, scratch, MTOK, CCH, kLen,
                lda, ldb, CCH, 4, 1,
                kLen, 0, (long long)kLen * ldb, 0, (long long)MTOK * CCH, 0, 1.f);
    reduce4_ln_kernel<<<MTOK, 256>>>(scratch, bias, res, tOut, s, bln, nOut);
}

extern "C" void kernel_launch(void* const* d_in, const int* in_sizes, int n_in,
                              void* d_out, int out_size) {
    const float* x      = (const float*)d_in[0];
    const float* ctx    = (const float*)d_in[1];
    const float* gn_s   = (const float*)d_in[2];
    const float* gn_b   = (const float*)d_in[3];
    const float* pin_w  = (const float*)d_in[4];
    const float* pin_b  = (const float*)d_in[5];
    const float* ln1_s  = (const float*)d_in[6];
    const float* ln1_b  = (const float*)d_in[7];
    const float* wq1    = (const float*)d_in[8];
    const float* wk1    = (const float*)d_in[9];
    const float* wv1    = (const float*)d_in[10];
    const float* wo1    = (const float*)d_in[11];
    const float* bo1    = (const float*)d_in[12];
    const float* ln2_s  = (const float*)d_in[13];
    const float* ln2_b  = (const float*)d_in[14];
    const float* wq2    = (const float*)d_in[15];
    const float* wk2    = (const float*)d_in[16];
    const float* wv2    = (const float*)d_in[17];
    const float* wo2    = (const float*)d_in[18];
    const float* bo2    = (const float*)d_in[19];
    const float* ln3_s  = (const float*)d_in[20];
    const float* ln3_b  = (const float*)d_in[21];
    const float* ff_w1  = (const float*)d_in[22];
    const float* ff_b1  = (const float*)d_in[23];
    const float* ff_w2  = (const float*)d_in[24];
    const float* ff_b2  = (const float*)d_in[25];
    const float* pout_w = (const float*)d_in[26];
    const float* pout_b = (const float*)d_in[27];
    float* out = (float*)d_out;

    float *t, *tmp, *qkv, *ao, *scores, *ffh, *ffa, *w3, *w2c, *w1i, *b1i;
    cudaGetSymbolAddress((void**)&t,      g_t);
    cudaGetSymbolAddress((void**)&tmp,    g_tmp);
    cudaGetSymbolAddress((void**)&qkv,    g_qkv);
    cudaGetSymbolAddress((void**)&ao,     g_ao);
    cudaGetSymbolAddress((void**)&scores, g_scores);
    cudaGetSymbolAddress((void**)&ffh,    g_ffh);
    cudaGetSymbolAddress((void**)&ffa,    g_ffa);
    cudaGetSymbolAddress((void**)&w3,     g_w3);
    cudaGetSymbolAddress((void**)&w2c,    g_w2c);
    cudaGetSymbolAddress((void**)&w1i,    g_w1i);
    cudaGetSymbolAddress((void**)&b1i,    g_b1i);

    cudaFuncSetAttribute(flash_kernel, cudaFuncAttributeMaxDynamicSharedMemorySize,
                         FA_SMEM_BYTES);

    const float attn_scale = 0.125f;
    const int LD3 = 3 * CCH, LD2 = 2 * CCH;

    cudaMemcpy2DAsync(w3,         LD3 * 4, wq1, CCH * 4, CCH * 4, CCH, cudaMemcpyDeviceToDevice);
    cudaMemcpy2DAsync(w3 + CCH,   LD3 * 4, wk1, CCH * 4, CCH * 4, CCH, cudaMemcpyDeviceToDevice);
    cudaMemcpy2DAsync(w3 + 2*CCH, LD3 * 4, wv1, CCH * 4, CCH * 4, CCH, cudaMemcpyDeviceToDevice);
    cudaMemcpy2DAsync(w2c,        LD2 * 4, wk2, CCH * 4, CCH * 4, CCH, cudaMemcpyDeviceToDevice);
    cudaMemcpy2DAsync(w2c + CCH,  LD2 * 4, wv2, CCH * 4, CCH * 4, CCH, cudaMemcpyDeviceToDevice);
    {
        size_t total = (size_t)CCH * FFD;
        prep_w1_kernel<<<(int)((total + 255) / 256), 256>>>(ff_w1, ff_b1, w1i, b1i);
    }

    groupnorm_kernel<<<BATCH * GN_GROUPS, 256>>>(x, gn_s, gn_b, tmp);
    launch_gemm_sk4_ln(tmp, pin_w, pin_b, nullptr, t, ffh, ln1_s, ln1_b, tmp, CCH, CCH, CCH);

    // ---- self-attention (flash) ----
    launch_gemm(false, 128, tmp, w3, nullptr, nullptr, qkv, MTOK, 3 * CCH, CCH,
                CCH, LD3, LD3, 1, 1, 0, 0, 0, 0, 0, 0, 1.f);
    {
        dim3 gf(1, 13, BATCH * HEADS);
        flash_kernel<<<gf, 256, FA_SMEM_BYTES>>>(qkv, ao);
    }
    launch_gemm_sk4_ln(ao, wo1, bo1, t, t, ffh, ln2_s, ln2_b, tmp, CCH, CCH, CCH);

    // ---- cross-attention ----
    launch_gemm_sk4(tmp, wq2, nullptr, nullptr, qkv, ffh, MTOK, CCH, CCH, CCH, CCH, LD3);
    launch_gemm(false, 128, ctx, w2c, nullptr, nullptr, qkv + CCH, BATCH * CTXL, 2 * CCH, CCH,
                CCH, LD2, LD3, 1, 1, 0, 0, 0, 0, 0, 0, 1.f);
    launch_gemm(true, 64, qkv, qkv + CCH, nullptr, nullptr, scores, HW, CTXL, DH,
                LD3, LD3, CTXP, BATCH * HEADS, HEADS,
                (long long)HW * LD3, DH, (long long)CTXL * LD3, DH,
                (long long)HEADS * HW * CTXP, (long long)HW * CTXP, attn_scale);
    {
        int nrows = BATCH * HEADS * HW;
        softmax_warp_kernel<<<(nrows + 7) / 8, 256>>>(scores);
    }
    launch_gemm(false, 64, scores, qkv + 2 * CCH, nullptr, nullptr, ao, HW, DH, CTXP,
                CTXP, LD3, CCH, BATCH * HEADS, HEADS,
                (long long)HEADS * HW * CTXP, (long long)HW * CTXP,
                (long long)CTXL * LD3, DH, (long long)HW * CCH, DH, 1.f);
    launch_gemm_sk4_ln(ao, wo2, bo2, t, t, ffh, ln3_s, ln3_b, tmp, CCH, CCH, CCH);

    // ---- GEGLU FF (ff1 fused geglu) ----
    launch_gemm(false, 128, tmp, w1i, b1i, nullptr, ffa, MTOK, 2 * FFD, CCH,
                CCH, 2 * FFD, FFD, 1, 1, 0, 0, 0, 0, 0, 0, 1.f, 1);
    launch_gemm_sk4(ffa, ff_w2, ff_b2, t, t, ffh, MTOK, CCH, FFD, FFD, CCH, CCH);

    // ---- proj_out (split-K4, fused reduce+transpose+residual) ----
    {
        int kLen = CCH / 4;
        launch_gemm(false, 128, t, pout_w, nullptr, nullptr, ffh, MTOK, CCH, kLen,
                    CCH, CCH, CCH, 4, 1,
                    kLen, 0, (long long)kLen * CCH, 0, (long long)MTOK * CCH, 0, 1.f);
        size_t MN = (size_t)MTOK * CCH;
        reduce4_final_kernel<<<(int)((MN + 255) / 256), 256>>>(ffh, pout_b, x, out);
    }
}